// round 2
// baseline (speedup 1.0000x reference)
#include <cuda_runtime.h>

// RRGraphConv: out = (feat + segment_sum(feat[src], dst)) @ W.T + b
// (radius is dead input: torch.ones_like zeroes the power-law weight)
//
// Inputs (metadata order): feat[N*64] f32, radius[E] f32 (unused),
//                          src[E] i32, dst[E] i32, W[128*64] f32, b[128] f32
// Output: out[N*128] f32

#define D_IN  64
#define D_OUT 128
#define MAX_NODES 100000
#define ROWS_PER_BLOCK 64

// Scratch mailbox (allocation-free per harness rules): h[node][k]
__device__ float g_h[(size_t)MAX_NODES * D_IN];

// K0: initialize mailbox to feat (folds the "+ feat" term; eps = 0)
__global__ void init_h_kernel(const float* __restrict__ feat, int n4) {
    int i = blockIdx.x * blockDim.x + threadIdx.x;
    if (i < n4) {
        reinterpret_cast<float4*>(g_h)[i] =
            reinterpret_cast<const float4*>(feat)[i];
    }
}

// K1: scatter-add feat[src] into g_h[dst].
// 8 threads per edge; each thread handles two float4 (16B) chunks of the
// 256B row -> 2 independent gathers (MLP=2) + 2 red.global.add.v4.f32.
__global__ void scatter_kernel(const float* __restrict__ feat,
                               const int*   __restrict__ src,
                               const int*   __restrict__ dst,
                               int E) {
    unsigned idx = blockIdx.x * blockDim.x + threadIdx.x;
    unsigned e = idx >> 3;
    if (e >= (unsigned)E) return;
    int c = (idx & 7) * 2;  // chunk pair: c, c+1 (of 16 float4 chunks)

    int s = __ldg(&src[e]);
    int d = __ldg(&dst[e]);

    const float4* srow = reinterpret_cast<const float4*>(feat + (size_t)s * D_IN);
    float4 v0 = __ldg(srow + c);
    float4 v1 = __ldg(srow + c + 1);

    float* p = g_h + (size_t)d * D_IN + (size_t)c * 4;
    asm volatile("red.global.add.v4.f32 [%0], {%1, %2, %3, %4};"
                 :: "l"(p), "f"(v0.x), "f"(v0.y), "f"(v0.z), "f"(v0.w)
                 : "memory");
    asm volatile("red.global.add.v4.f32 [%0], {%1, %2, %3, %4};"
                 :: "l"(p + 4), "f"(v1.x), "f"(v1.y), "f"(v1.z), "f"(v1.w)
                 : "memory");
}

// K2: out[row, j] = dot(g_h[row, :], W[j, :]) + b[j]
// 128 threads/block; thread j owns output column j, W[j,:] in registers.
// Rows staged 2-at-a-time in smem (all 128 threads cooperate on the load),
// read back as LDS.128 broadcasts (conflict-free).
__global__ __launch_bounds__(128)
void gemm_kernel(const float* __restrict__ W,
                 const float* __restrict__ b,
                 float* __restrict__ out,
                 int N) {
    __shared__ float sx[2][D_IN];
    const int j = threadIdx.x;  // 0..127 = output column

    float w[D_IN];
    const float4* Wr = reinterpret_cast<const float4*>(W + (size_t)j * D_IN);
#pragma unroll
    for (int k = 0; k < D_IN / 4; k++) {
        float4 t = __ldg(&Wr[k]);
        w[4 * k + 0] = t.x;
        w[4 * k + 1] = t.y;
        w[4 * k + 2] = t.z;
        w[4 * k + 3] = t.w;
    }
    const float bias = __ldg(&b[j]);

    const int row0 = blockIdx.x * ROWS_PER_BLOCK;

    for (int r = 0; r < ROWS_PER_BLOCK; r += 2) {
        const int row = row0 + r;
        if (row >= N) break;

        __syncthreads();  // previous iteration's smem reads complete
        {
            int rr = j >> 6;       // 0 or 1
            int k  = j & 63;       // 0..63
            if (row + rr < N)
                sx[rr][k] = g_h[(size_t)(row + rr) * D_IN + k];
        }
        __syncthreads();

#pragma unroll
        for (int rr = 0; rr < 2; rr++) {
            if (row + rr >= N) break;
            float a0 = 0.f, a1 = 0.f, a2 = 0.f, a3 = 0.f;
            const float4* xr = reinterpret_cast<const float4*>(sx[rr]);
#pragma unroll
            for (int k4 = 0; k4 < D_IN / 4; k4++) {
                float4 x = xr[k4];  // LDS.128 broadcast
                a0 = fmaf(w[4 * k4 + 0], x.x, a0);
                a1 = fmaf(w[4 * k4 + 1], x.y, a1);
                a2 = fmaf(w[4 * k4 + 2], x.z, a2);
                a3 = fmaf(w[4 * k4 + 3], x.w, a3);
            }
            out[(size_t)(row + rr) * D_OUT + j] = (a0 + a1) + (a2 + a3) + bias;
        }
    }
}

extern "C" void kernel_launch(void* const* d_in, const int* in_sizes, int n_in,
                              void* d_out, int out_size) {
    const float* feat = (const float*)d_in[0];
    // d_in[1] = radius (unused: weight is ones_like'd away)
    const int*   src  = (const int*)d_in[2];
    const int*   dst  = (const int*)d_in[3];
    const float* W    = (const float*)d_in[4];
    const float* b    = (const float*)d_in[5];
    float* out = (float*)d_out;

    const int N = in_sizes[0] / D_IN;   // 100000
    const int E = in_sizes[2];          // 1600000

    // K0: g_h = feat
    {
        int n4 = (N * D_IN) / 4;
        int threads = 256;
        int blocks = (n4 + threads - 1) / threads;
        init_h_kernel<<<blocks, threads>>>(feat, n4);
    }

    // K1: g_h[dst] += feat[src]
    {
        long long total = (long long)E * 8;
        int threads = 256;
        int blocks = (int)((total + threads - 1) / threads);
        scatter_kernel<<<blocks, threads>>>(feat, src, dst, E);
    }

    // K2: out = g_h @ W.T + b
    {
        int blocks = (N + ROWS_PER_BLOCK - 1) / ROWS_PER_BLOCK;
        gemm_kernel<<<blocks, 128>>>(W, b, out, N);
    }
}